// round 5
// baseline (speedup 1.0000x reference)
#include <cuda_runtime.h>
#include <cstdint>

#define DIM 128
#define NPAD 50048          // ceil(50000/128)*128
#define NREL 9              // 8 relations + self-loop

// hr[r][node][128] scratch, r in 0..7  (205 MB static device global)
__device__ float g_hr[(size_t)8 * NPAD * DIM];

// Padded smem strides (floats): conflict-free fragment loads.
#define XS_STRIDE 132
#define WS_STRIDE 136
#define SMEM_FLOATS (128 * XS_STRIDE + 2 * 128 * WS_STRIDE)
#define SMEM_BYTES (SMEM_FLOATS * 4)   // 206848 B

#define NTHREADS 512

__device__ __forceinline__ uint32_t f2tf32(float f) {
    uint32_t o;
    asm("cvt.rna.tf32.f32 %0, %1;" : "=r"(o) : "f"(f));
    return o;
}

#define MMA_TF32(d, a, b0, b1)                                                  \
    asm volatile("mma.sync.aligned.m16n8k8.row.col.f32.tf32.tf32.f32 "          \
                 "{%0,%1,%2,%3}, {%4,%5,%6,%7}, {%8,%9}, {%0,%1,%2,%3};"        \
                 : "+f"((d)[0]), "+f"((d)[1]), "+f"((d)[2]), "+f"((d)[3])       \
                 : "r"((a)[0]), "r"((a)[1]), "r"((a)[2]), "r"((a)[3]),          \
                   "r"(b0), "r"(b1))

__device__ __forceinline__ void cp16(float* s, const float* g) {
    uint32_t sa = (uint32_t)__cvta_generic_to_shared(s);
    asm volatile("cp.async.cg.shared.global [%0], [%1], 16;" :: "r"(sa), "l"(g));
}

__device__ __forceinline__ void issue_w(float* buf, const float* wr, int tid) {
#pragma unroll
    for (int i = tid; i < 128 * 32; i += NTHREADS) {
        int r = i >> 5, c4 = i & 31;
        cp16(buf + r * WS_STRIDE + c4 * 4, wr + r * DIM + c4 * 4);
    }
    asm volatile("cp.async.commit_group;" ::: "memory");
}

// ---------------------------------------------------------------------------
// GEMM: per CTA, 128 node rows x all 9 relations. 512 threads = 16 warps,
// warp tile 16x64. rel 0..7 -> g_hr[rel]; rel 8 -> out = X@selfW + bias.
// ---------------------------------------------------------------------------
__global__ void __launch_bounds__(NTHREADS, 1)
rgcn_gemm_mma(const float* __restrict__ x,
              const float* __restrict__ w,
              const float* __restrict__ sw,
              const float* __restrict__ bias,
              float* __restrict__ out,
              int n_nodes) {
    extern __shared__ float smem[];
    float* Xs  = smem;                         // [128][XS_STRIDE] (tf32 bits)
    float* Ws0 = smem + 128 * XS_STRIDE;       // [128][WS_STRIDE]
    float* Ws1 = Ws0 + 128 * WS_STRIDE;

    const int tid = threadIdx.x;
    const int wid = tid >> 5, lane = tid & 31;
    const int row0 = blockIdx.x * 128;
    const int wm = (wid & 7) * 16;   // 8 M-blocks of 16 rows
    const int wn = (wid >> 3) * 64;  // 2 N-blocks of 64 cols

    issue_w(Ws0, w, tid);
    issue_w(Ws1, w + DIM * DIM, tid);

    // X tile (tf32-converted once; zero-pad tail rows)
#pragma unroll
    for (int i = tid; i < 128 * 32; i += NTHREADS) {
        int r = i >> 5, c4 = i & 31;
        int node = row0 + r;
        float4 v = (node < n_nodes) ? *(const float4*)(x + (size_t)node * DIM + c4 * 4)
                                    : make_float4(0.f, 0.f, 0.f, 0.f);
        uint32_t* d = (uint32_t*)(Xs + r * XS_STRIDE + c4 * 4);
        d[0] = f2tf32(v.x); d[1] = f2tf32(v.y); d[2] = f2tf32(v.z); d[3] = f2tf32(v.w);
    }

    const int lr = lane >> 2;          // 0..7
    const int lk = lane & 3;           // 0..3
    const int lc = (lane & 3) * 2;

    for (int rel = 0; rel < NREL; ++rel) {
        if (rel == NREL - 1) asm volatile("cp.async.wait_group 0;" ::: "memory");
        else                 asm volatile("cp.async.wait_group 1;" ::: "memory");
        __syncthreads();

        const float* Wb = (rel & 1) ? Ws1 : Ws0;

        float c[8][4];
#pragma unroll
        for (int i = 0; i < 8; i++)
#pragma unroll
            for (int j = 0; j < 4; j++) c[i][j] = 0.0f;

#pragma unroll 4
        for (int ks = 0; ks < 16; ks++) {
            const int k0 = ks * 8;
            uint32_t a[4];
            {
                const uint32_t* xr = (const uint32_t*)Xs + (wm + lr) * XS_STRIDE + k0 + lk;
                a[0] = xr[0];
                a[1] = xr[8 * XS_STRIDE];
                a[2] = xr[4];
                a[3] = xr[8 * XS_STRIDE + 4];
            }
#pragma unroll
            for (int nt = 0; nt < 8; nt++) {
                const float* wp = Wb + (k0 + lk) * WS_STRIDE + wn + nt * 8 + lr;
                uint32_t b0 = f2tf32(wp[0]);
                uint32_t b1 = f2tf32(wp[4 * WS_STRIDE]);
                MMA_TF32(c[nt], a, b0, b1);
            }
        }

        __syncthreads();   // all warps done reading Wb
        if (rel + 2 < NREL) {
            const float* nw = (rel + 2 < 8) ? (w + (size_t)(rel + 2) * DIM * DIM) : sw;
            issue_w((float*)Wb, nw, tid);
        }

        if (rel < 8) {
            float* base = g_hr + ((size_t)rel * NPAD + row0) * DIM;
#pragma unroll
            for (int nt = 0; nt < 8; nt++) {
                int r = wm + lr;
                int cc = wn + nt * 8 + lc;
                *(float2*)(base + (size_t)r * DIM + cc)       = make_float2(c[nt][0], c[nt][1]);
                *(float2*)(base + (size_t)(r + 8) * DIM + cc) = make_float2(c[nt][2], c[nt][3]);
            }
        } else {
#pragma unroll
            for (int nt = 0; nt < 8; nt++) {
                int r = wm + lr;
                int cc = wn + nt * 8 + lc;
                float b0 = bias[cc], b1 = bias[cc + 1];
                int g0 = row0 + r, g1 = row0 + r + 8;
                if (g0 < n_nodes)
                    *(float2*)(out + (size_t)g0 * DIM + cc) =
                        make_float2(c[nt][0] + b0, c[nt][1] + b1);
                if (g1 < n_nodes)
                    *(float2*)(out + (size_t)g1 * DIM + cc) =
                        make_float2(c[nt][2] + b0, c[nt][3] + b1);
            }
        }
    }
}

// ---------------------------------------------------------------------------
// Scatter: 2 edges per warp (independent 512B gathers for MLP), red.v4 out.
// ---------------------------------------------------------------------------
__global__ void rgcn_scatter(const int* __restrict__ ei,
                             const int* __restrict__ et,
                             float* __restrict__ out,
                             int n_edges) {
    int gw = (blockIdx.x * blockDim.x + threadIdx.x) >> 5;
    int lane = threadIdx.x & 31;
    int e0 = gw * 2;
    if (e0 >= n_edges) return;
    int e1 = e0 + 1;
    bool has1 = (e1 < n_edges);

    int s0 = ei[e0], d0 = ei[n_edges + e0], r0 = et[e0];
    int s1 = has1 ? ei[e1] : 0;
    int d1 = has1 ? ei[n_edges + e1] : 0;
    int r1 = has1 ? et[e1] : 0;

    const float* p0 = g_hr + ((size_t)r0 * NPAD + (size_t)s0) * DIM + lane * 4;
    const float* p1 = g_hr + ((size_t)r1 * NPAD + (size_t)s1) * DIM + lane * 4;
    float4 v0 = *(const float4*)p0;
    float4 v1 = has1 ? *(const float4*)p1 : make_float4(0.f, 0.f, 0.f, 0.f);

    float* q0 = out + (size_t)d0 * DIM + lane * 4;
    asm volatile("red.global.add.v4.f32 [%0], {%1, %2, %3, %4};"
                 :: "l"(q0), "f"(v0.x), "f"(v0.y), "f"(v0.z), "f"(v0.w) : "memory");
    if (has1) {
        float* q1 = out + (size_t)d1 * DIM + lane * 4;
        asm volatile("red.global.add.v4.f32 [%0], {%1, %2, %3, %4};"
                     :: "l"(q1), "f"(v1.x), "f"(v1.y), "f"(v1.z), "f"(v1.w) : "memory");
    }
}

__global__ void rgcn_relu(float* __restrict__ out, int n4) {
    int i = blockIdx.x * blockDim.x + threadIdx.x;
    if (i < n4) {
        float4 v = ((float4*)out)[i];
        v.x = fmaxf(v.x, 0.0f); v.y = fmaxf(v.y, 0.0f);
        v.z = fmaxf(v.z, 0.0f); v.w = fmaxf(v.w, 0.0f);
        ((float4*)out)[i] = v;
    }
}

// ---------------------------------------------------------------------------
extern "C" void kernel_launch(void* const* d_in, const int* in_sizes, int n_in,
                              void* d_out, int out_size) {
    const float* x    = (const float*)d_in[0];
    const float* w    = (const float*)d_in[1];
    const float* sw   = (const float*)d_in[2];
    const float* bias = (const float*)d_in[3];
    const int* ei = (const int*)d_in[4];
    const int* et = (const int*)d_in[5];

    int n_nodes = in_sizes[0] / DIM;
    int n_edges = in_sizes[5];
    float* out = (float*)d_out;

    static int smem_set = 0;
    if (!smem_set) {
        cudaFuncSetAttribute(rgcn_gemm_mma, cudaFuncAttributeMaxDynamicSharedMemorySize,
                             SMEM_BYTES);
        smem_set = 1;
    }

    int nb = (n_nodes + 127) / 128;
    rgcn_gemm_mma<<<nb, NTHREADS, SMEM_BYTES>>>(x, w, sw, bias, out, n_nodes);

    int n_warps = (n_edges + 1) / 2;
    long long total_threads = (long long)n_warps * 32;
    int blocks = (int)((total_threads + 255) / 256);
    rgcn_scatter<<<blocks, 256>>>(ei, et, out, n_edges);

    int n4 = n_nodes * DIM / 4;
    rgcn_relu<<<(n4 + 255) / 256, 256>>>(out, n4);
}